// round 2
// baseline (speedup 1.0000x reference)
#include <cuda_runtime.h>
#include <math.h>

// ---------------- problem constants ----------------
#define BATCH   8
#define HG      64
#define WSZ     8
#define SHIFT   4
#define CDIM    384
#define HEADS   12
#define HDIM    32          // CDIM / HEADS
#define NTOK    64          // WSZ*WSZ tokens per window
#define NWIN    64          // (64/8)^2 windows per image
#define BW      (BATCH*NWIN)        // 512 windows total
#define MTOK    (BATCH*HG*HG)       // 32768 tokens
#define NQKV    (3*CDIM)            // 1152
#define HID     (4*CDIM)            // 1536
#define QS      (BW*HEADS*NTOK*HDIM) // 12,582,912 elems per q/k/v

// ---------------- scratch (static device memory; no allocs) ----------------
__device__ float g_qkv[3*QS];          // q,k,v   [which][bw][head][tok][d]
__device__ float g_ao [MTOK*CDIM];     // attention out, window order
__device__ float g_tmp[MTOK*CDIM];     // pre-LN buffer (proj out / fc2 out)
__device__ float g_x1 [MTOK*CDIM];     // post-attn residual
__device__ float g_h  [MTOK*HID];      // mlp hidden
__device__ float g_rpb[HEADS*NTOK*NTOK];

// window-order row m  ->  original token index (roll + window partition, both dirs)
__device__ __forceinline__ int winperm(int m) {
    int bw = m >> 6, n = m & 63;
    int batch = bw >> 6, w = bw & 63;
    int hi = w >> 3, wj = w & 7;
    int r = n >> 3, c = n & 7;
    int h  = ((hi << 3) + r + SHIFT) & 63;
    int ww = ((wj << 3) + c + SHIFT) & 63;
    return (batch << 12) + (h << 6) + ww;
}

__device__ __forceinline__ int lab(int x) { return x < 56 ? 0 : (x < 60 ? 1 : 2); }

// ---------------- relative position bias table ----------------
__global__ void rpb_kernel(const float* __restrict__ w1, const float* __restrict__ b1,
                           const float* __restrict__ w2) {
    __shared__ float cpb[225][HEADS];
    int t = threadIdx.x;
    if (t < 225) {
        int a = t / 15, b = t % 15;
        float t0 = (float)(a - 7) / 7.0f * 8.0f;
        float t1 = (float)(b - 7) / 7.0f * 8.0f;
        t0 = copysignf(log2f(fabsf(t0) + 1.0f) / 3.0f, t0);
        t1 = copysignf(log2f(fabsf(t1) + 1.0f) / 3.0f, t1);
        float acc[HEADS];
        #pragma unroll
        for (int hh = 0; hh < HEADS; hh++) acc[hh] = 0.f;
        for (int j = 0; j < 512; j++) {
            float hj = fmaxf(w1[2*j] * t0 + w1[2*j+1] * t1 + b1[j], 0.f);
            #pragma unroll
            for (int hh = 0; hh < HEADS; hh++) acc[hh] += hj * w2[hh*512 + j];
        }
        #pragma unroll
        for (int hh = 0; hh < HEADS; hh++) cpb[t][hh] = acc[hh];
    }
    __syncthreads();
    for (int idx = t; idx < HEADS*NTOK*NTOK; idx += blockDim.x) {
        int h = idx >> 12, rem = idx & 4095;
        int n = rem >> 6, m = rem & 63;
        int ii = ((n >> 3) - (m >> 3) + 7) * 15 + ((n & 7) - (m & 7) + 7);
        g_rpb[idx] = 16.0f / (1.0f + expf(-cpb[ii][h]));
    }
}

// ---------------- generic 64x64 SGEMM: C[M,N] = A[M,K] * B[N,K]^T + epilogue ----------------
// MODE 0: QKV  (gather A rows via winperm, bias=q_bias/0/v_bias, scatter to q/k/v layout)
// MODE 1: proj (bias + scatter output rows via winperm)
// MODE 2: bias
// MODE 3: bias + exact gelu
template<int MODE, bool GATHER>
__global__ void __launch_bounds__(256)
gemm64(const float* __restrict__ A, const float* __restrict__ Bm,
       const float* __restrict__ bias, const float* __restrict__ bias2,
       float* __restrict__ C, int M, int N, int K) {
    __shared__ float As[16][68];
    __shared__ float Bs[16][68];
    int tid = threadIdx.x;
    int n0 = blockIdx.x * 64;
    int m0 = blockIdx.y * 64;

    int lrow = tid >> 2;            // 0..63
    int lk4  = (tid & 3) << 2;      // 0,4,8,12
    int arow = m0 + lrow;
    int asrc = GATHER ? winperm(arow) : arow;
    const float* Aptr = A  + (size_t)asrc * K + lk4;
    const float* Bptr = Bm + (size_t)(n0 + lrow) * K + lk4;

    int tx = tid & 15, ty = tid >> 4;
    float acc[4][4];
    #pragma unroll
    for (int i = 0; i < 4; i++)
        #pragma unroll
        for (int j = 0; j < 4; j++) acc[i][j] = 0.f;

    for (int k0 = 0; k0 < K; k0 += 16) {
        float4 av = *(const float4*)(Aptr + k0);
        float4 bv = *(const float4*)(Bptr + k0);
        As[lk4+0][lrow] = av.x; As[lk4+1][lrow] = av.y;
        As[lk4+2][lrow] = av.z; As[lk4+3][lrow] = av.w;
        Bs[lk4+0][lrow] = bv.x; Bs[lk4+1][lrow] = bv.y;
        Bs[lk4+2][lrow] = bv.z; Bs[lk4+3][lrow] = bv.w;
        __syncthreads();
        #pragma unroll
        for (int k = 0; k < 16; k++) {
            float a[4], b[4];
            #pragma unroll
            for (int i = 0; i < 4; i++) { a[i] = As[k][ty*4+i]; b[i] = Bs[k][tx*4+i]; }
            #pragma unroll
            for (int i = 0; i < 4; i++)
                #pragma unroll
                for (int j = 0; j < 4; j++) acc[i][j] += a[i] * b[j];
        }
        __syncthreads();
    }

    #pragma unroll
    for (int i = 0; i < 4; i++) {
        int m = m0 + ty*4 + i;
        #pragma unroll
        for (int j = 0; j < 4; j++) {
            int n = n0 + tx*4 + j;
            float v = acc[i][j];
            if (MODE == 0) {                 // QKV: split + bias + scatter
                int which = n / CDIM;
                int rem   = n - which * CDIM;
                if (which == 0) v += bias[rem];
                else if (which == 2) v += bias2[rem];
                int bw = m >> 6, tok = m & 63;
                int head = rem >> 5, dd = rem & 31;
                C[which*QS + (((bw*HEADS) + head)*NTOK + tok)*HDIM + dd] = v;
            } else if (MODE == 1) {          // proj: bias + scatter rows
                v += bias[n];
                C[(size_t)winperm(m) * N + n] = v;
            } else if (MODE == 2) {          // plain bias
                v += bias[n];
                C[(size_t)m * N + n] = v;
            } else {                         // bias + exact gelu
                v += bias[n];
                v = 0.5f * v * (1.0f + erff(v * 0.70710678118654752f));
                C[(size_t)m * N + n] = v;
            }
        }
    }
}

// ---------------- fused attention: one block per (window, head) ----------------
__global__ void __launch_bounds__(64)
attn_kernel(const float* __restrict__ flex) {
    int b = blockIdx.x;      // window 0..511
    int h = blockIdx.y;      // head 0..11
    int n = threadIdx.x;     // token 0..63

    __shared__ float kn[NTOK][HDIM+1];
    __shared__ float vs[NTOK][HDIM+1];
    __shared__ int   grp[NTOK];
    __shared__ float sscale;

    size_t base = ((size_t)(b*HEADS + h)) * NTOK * HDIM;
    const float* qp = g_qkv + base;
    const float* kp = g_qkv + QS   + base;
    const float* vp = g_qkv + 2*QS + base;

    // q row -> registers (normalized)
    float qr[HDIM];
    float qn2 = 0.f;
    #pragma unroll
    for (int d = 0; d < HDIM; d++) { qr[d] = qp[n*HDIM + d]; qn2 += qr[d]*qr[d]; }
    float qinv = 1.0f / fmaxf(sqrtf(qn2), 1e-12f);
    #pragma unroll
    for (int d = 0; d < HDIM; d++) qr[d] *= qinv;

    // k row -> smem (normalized), v row -> smem
    float kn2 = 0.f;
    float kr[HDIM];
    #pragma unroll
    for (int d = 0; d < HDIM; d++) { kr[d] = kp[n*HDIM + d]; kn2 += kr[d]*kr[d]; }
    float kinv = 1.0f / fmaxf(sqrtf(kn2), 1e-12f);
    #pragma unroll
    for (int d = 0; d < HDIM; d++) kn[n][d] = kr[d] * kinv;
    #pragma unroll
    for (int d = 0; d < HDIM; d++) vs[n][d] = vp[n*HDIM + d];

    // shift-mask group label for this token
    {
        int w = b & 63;
        int hh = (w >> 3) * 8 + (n >> 3);
        int ww = (w & 7) * 8 + (n & 7);
        grp[n] = lab(hh) * 3 + lab(ww);
    }
    if (n == 0) sscale = expf(fminf(flex[h], 4.6051701859880914f));  // log(100)
    __syncthreads();

    float scale = sscale;
    int g1 = grp[n];
    const float* rp = g_rpb + (h*NTOK + n)*NTOK;

    float s[NTOK];
    float mx = -1e30f;
    #pragma unroll
    for (int m = 0; m < NTOK; m++) {
        float dot = 0.f;
        #pragma unroll
        for (int d = 0; d < HDIM; d++) dot += qr[d] * kn[m][d];
        float val = dot * scale + rp[m] + (grp[m] == g1 ? 0.f : -100.f);
        s[m] = val;
        mx = fmaxf(mx, val);
    }
    float sum = 0.f;
    #pragma unroll
    for (int m = 0; m < NTOK; m++) { s[m] = expf(s[m] - mx); sum += s[m]; }
    float inv = 1.0f / sum;

    float o[HDIM];
    #pragma unroll
    for (int d = 0; d < HDIM; d++) o[d] = 0.f;
    #pragma unroll
    for (int m = 0; m < NTOK; m++) {
        float p = s[m] * inv;
        #pragma unroll
        for (int d = 0; d < HDIM; d++) o[d] += p * vs[m][d];
    }

    float* dst = g_ao + (size_t)(b*NTOK + n) * CDIM + h*HDIM;
    #pragma unroll
    for (int d = 0; d < HDIM; d++) dst[d] = o[d];
}

// ---------------- residual + layernorm: out = res + LN(y)*g + b ----------------
__global__ void __launch_bounds__(128)
ln_add_kernel(const float* __restrict__ y, const float* __restrict__ res,
              const float* __restrict__ g, const float* __restrict__ b,
              float* __restrict__ out) {
    int row = blockIdx.x;
    int t = threadIdx.x;
    const float* yr = y + (size_t)row * CDIM;
    float v[3];
    float s = 0.f;
    #pragma unroll
    for (int i = 0; i < 3; i++) { v[i] = yr[t + i*128]; s += v[i]; }

    __shared__ float sh[5];
    int lane = t & 31, wid = t >> 5;
    #pragma unroll
    for (int o = 16; o > 0; o >>= 1) s += __shfl_down_sync(0xffffffffu, s, o);
    if (lane == 0) sh[wid] = s;
    __syncthreads();
    if (t == 0) sh[4] = sh[0] + sh[1] + sh[2] + sh[3];
    __syncthreads();
    float mean = sh[4] * (1.0f / CDIM);

    float s2 = 0.f;
    #pragma unroll
    for (int i = 0; i < 3; i++) { float d = v[i] - mean; s2 += d*d; }
    __syncthreads();
    #pragma unroll
    for (int o = 16; o > 0; o >>= 1) s2 += __shfl_down_sync(0xffffffffu, s2, o);
    if (lane == 0) sh[wid] = s2;
    __syncthreads();
    if (t == 0) sh[4] = sh[0] + sh[1] + sh[2] + sh[3];
    __syncthreads();
    float rstd = rsqrtf(sh[4] * (1.0f / CDIM) + 1e-5f);

    const float* rr = res + (size_t)row * CDIM;
    float* orow = out + (size_t)row * CDIM;
    #pragma unroll
    for (int i = 0; i < 3; i++) {
        int col = t + i*128;
        orow[col] = rr[col] + (v[i] - mean) * rstd * g[col] + b[col];
    }
}

// ---------------- launch ----------------
extern "C" void kernel_launch(void* const* d_in, const int* in_sizes, int n_in,
                              void* d_out, int out_size) {
    const float* x      = (const float*)d_in[0];
    const float* qkv_w  = (const float*)d_in[1];
    const float* q_bias = (const float*)d_in[2];
    const float* v_bias = (const float*)d_in[3];
    const float* flex   = (const float*)d_in[4];
    const float* cpb_w1 = (const float*)d_in[5];
    const float* cpb_b1 = (const float*)d_in[6];
    const float* cpb_w2 = (const float*)d_in[7];
    const float* proj_w = (const float*)d_in[8];
    const float* proj_b = (const float*)d_in[9];
    const float* n1g    = (const float*)d_in[10];
    const float* n1b    = (const float*)d_in[11];
    const float* n2g    = (const float*)d_in[12];
    const float* n2b    = (const float*)d_in[13];
    const float* fc1w   = (const float*)d_in[14];
    const float* fc1b   = (const float*)d_in[15];
    const float* fc2w   = (const float*)d_in[16];
    const float* fc2b   = (const float*)d_in[17];
    float* out = (float*)d_out;

    float *p_qkv, *p_ao, *p_tmp, *p_x1, *p_h;
    cudaGetSymbolAddress((void**)&p_qkv, g_qkv);
    cudaGetSymbolAddress((void**)&p_ao,  g_ao);
    cudaGetSymbolAddress((void**)&p_tmp, g_tmp);
    cudaGetSymbolAddress((void**)&p_x1,  g_x1);
    cudaGetSymbolAddress((void**)&p_h,   g_h);

    // 1. relative position bias table
    rpb_kernel<<<1, 256>>>(cpb_w1, cpb_b1, cpb_w2);

    // 2. roll + window-partition + QKV GEMM (gather) -> q/k/v
    gemm64<0, true><<<dim3(NQKV/64, MTOK/64), 256>>>(
        x, qkv_w, q_bias, v_bias, p_qkv, MTOK, NQKV, CDIM);

    // 3. fused cosine attention
    attn_kernel<<<dim3(BW, HEADS), 64>>>(flex);

    // 4. proj GEMM + window-reverse scatter
    gemm64<1, false><<<dim3(CDIM/64, MTOK/64), 256>>>(
        p_ao, proj_w, proj_b, nullptr, p_tmp, MTOK, CDIM, CDIM);

    // 5. x1 = x + LN(proj_out)
    ln_add_kernel<<<MTOK, 128>>>(p_tmp, x, n1g, n1b, p_x1);

    // 6. fc1 + gelu
    gemm64<3, false><<<dim3(HID/64, MTOK/64), 256>>>(
        p_x1, fc1w, fc1b, nullptr, p_h, MTOK, HID, CDIM);

    // 7. fc2
    gemm64<2, false><<<dim3(CDIM/64, MTOK/64), 256>>>(
        p_h, fc2w, fc2b, nullptr, p_tmp, MTOK, CDIM, HID);

    // 8. out = x1 + LN(fc2_out)
    ln_add_kernel<<<MTOK, 128>>>(p_tmp, p_x1, n2g, n2b, out);
}

// round 3
// speedup vs baseline: 1.7513x; 1.7513x over previous
#include <cuda_runtime.h>
#include <math.h>

// ---------------- problem constants ----------------
#define BATCH   8
#define HG      64
#define WSZ     8
#define SHIFT   4
#define CDIM    384
#define HEADS   12
#define HDIM    32          // CDIM / HEADS
#define NTOK    64          // WSZ*WSZ tokens per window
#define NWIN    64          // (64/8)^2 windows per image
#define BW      (BATCH*NWIN)        // 512 windows total
#define MTOK    (BATCH*HG*HG)       // 32768 tokens
#define NQKV    (3*CDIM)            // 1152
#define HID     (4*CDIM)            // 1536
#define QS      (BW*HEADS*NTOK*HDIM) // elems per q/k/v

// ---------------- scratch (static device memory; no allocs) ----------------
__device__ float g_qkv[3*QS];          // q,k,v   [which][bw][head][tok][d]
__device__ float g_ao [MTOK*CDIM];     // attention out, window order
__device__ float g_tmp[MTOK*CDIM];     // pre-LN buffer (proj out / fc2 out)
__device__ float g_x1 [MTOK*CDIM];     // post-attn residual
__device__ float g_h  [MTOK*HID];      // mlp hidden
__device__ float g_rpb[HEADS*NTOK*NTOK];

// window-order row m  ->  original token index (roll + window partition)
__device__ __forceinline__ int winperm(int m) {
    int bw = m >> 6, n = m & 63;
    int batch = bw >> 6, w = bw & 63;
    int hi = w >> 3, wj = w & 7;
    int r = n >> 3, c = n & 7;
    int h  = ((hi << 3) + r + SHIFT) & 63;
    int ww = ((wj << 3) + c + SHIFT) & 63;
    return (batch << 12) + (h << 6) + ww;
}

__device__ __forceinline__ int lab(int x) { return x < 56 ? 0 : (x < 60 ? 1 : 2); }

__device__ __forceinline__ unsigned f2tf(float x) {
    unsigned r;
    asm("cvt.rna.tf32.f32 %0, %1;" : "=r"(r) : "f"(x));
    return r;
}

// ---------------- relative position bias table ----------------
__global__ void rpb_kernel(const float* __restrict__ w1, const float* __restrict__ b1,
                           const float* __restrict__ w2) {
    __shared__ float cpb[225][HEADS];
    int t = threadIdx.x;
    if (t < 225) {
        int a = t / 15, b = t % 15;
        float t0 = (float)(a - 7) / 7.0f * 8.0f;
        float t1 = (float)(b - 7) / 7.0f * 8.0f;
        t0 = copysignf(log2f(fabsf(t0) + 1.0f) / 3.0f, t0);
        t1 = copysignf(log2f(fabsf(t1) + 1.0f) / 3.0f, t1);
        float acc[HEADS];
        #pragma unroll
        for (int hh = 0; hh < HEADS; hh++) acc[hh] = 0.f;
        for (int j = 0; j < 512; j++) {
            float hj = fmaxf(w1[2*j] * t0 + w1[2*j+1] * t1 + b1[j], 0.f);
            #pragma unroll
            for (int hh = 0; hh < HEADS; hh++) acc[hh] += hj * w2[hh*512 + j];
        }
        #pragma unroll
        for (int hh = 0; hh < HEADS; hh++) cpb[t][hh] = acc[hh];
    }
    __syncthreads();
    for (int idx = t; idx < HEADS*NTOK*NTOK; idx += blockDim.x) {
        int h = idx >> 12, rem = idx & 4095;
        int n = rem >> 6, m = rem & 63;
        int ii = ((n >> 3) - (m >> 3) + 7) * 15 + ((n & 7) - (m & 7) + 7);
        g_rpb[idx] = 16.0f / (1.0f + expf(-cpb[ii][h]));
    }
}

// ---------------- tf32 tensor-core GEMM: C[M,N] = A[M,K]*B[N,K]^T + epilogue ----
// Tile 128x128x16, 256 threads = 8 warps (4 x 2), warp tile 32x64.
// MODE 0: QKV (gather rows, q/v bias, scatter to q/k/v)   MODE 1: proj (bias + row scatter)
// MODE 2: bias                                            MODE 3: bias + exact gelu
template<int MODE, bool GATHER>
__global__ void __launch_bounds__(256)
tgemm(const float* __restrict__ A, const float* __restrict__ Bm,
      const float* __restrict__ bias, const float* __restrict__ bias2,
      float* __restrict__ C, int M, int N, int K) {
    __shared__ unsigned As[16][132];
    __shared__ unsigned Bs[16][132];

    int tid  = threadIdx.x;
    int lane = tid & 31;
    int warp = tid >> 5;
    int n0 = blockIdx.x * 128;
    int m0 = blockIdx.y * 128;
    int wm0 = (warp & 3) * 32;   // warp row offset
    int wn0 = (warp >> 2) * 64;  // warp col offset

    // global->smem mapping: 2 float4 per thread per tile
    int r0 = tid >> 2;                 // 0..63
    int c4 = (tid & 3) << 2;           // 0,4,8,12
    int asrc0 = GATHER ? winperm(m0 + r0)      : (m0 + r0);
    int asrc1 = GATHER ? winperm(m0 + r0 + 64) : (m0 + r0 + 64);
    const float* Ap0 = A + (size_t)asrc0 * K + c4;
    const float* Ap1 = A + (size_t)asrc1 * K + c4;
    const float* Bp0 = Bm + (size_t)(n0 + r0) * K + c4;
    const float* Bp1 = Bm + (size_t)(n0 + r0 + 64) * K + c4;

    float acc[2][8][4];
    #pragma unroll
    for (int i = 0; i < 2; i++)
        #pragma unroll
        for (int j = 0; j < 8; j++)
            #pragma unroll
            for (int q = 0; q < 4; q++) acc[i][j][q] = 0.f;

    int grp = lane >> 2, qk = lane & 3;

    for (int k0 = 0; k0 < K; k0 += 16) {
        float4 a0 = *(const float4*)(Ap0 + k0);
        float4 a1 = *(const float4*)(Ap1 + k0);
        float4 b0 = *(const float4*)(Bp0 + k0);
        float4 b1 = *(const float4*)(Bp1 + k0);
        As[c4+0][r0] = f2tf(a0.x); As[c4+1][r0] = f2tf(a0.y);
        As[c4+2][r0] = f2tf(a0.z); As[c4+3][r0] = f2tf(a0.w);
        As[c4+0][r0+64] = f2tf(a1.x); As[c4+1][r0+64] = f2tf(a1.y);
        As[c4+2][r0+64] = f2tf(a1.z); As[c4+3][r0+64] = f2tf(a1.w);
        Bs[c4+0][r0] = f2tf(b0.x); Bs[c4+1][r0] = f2tf(b0.y);
        Bs[c4+2][r0] = f2tf(b0.z); Bs[c4+3][r0] = f2tf(b0.w);
        Bs[c4+0][r0+64] = f2tf(b1.x); Bs[c4+1][r0+64] = f2tf(b1.y);
        Bs[c4+2][r0+64] = f2tf(b1.z); Bs[c4+3][r0+64] = f2tf(b1.w);
        __syncthreads();

        #pragma unroll
        for (int kk = 0; kk < 16; kk += 8) {
            unsigned af[2][4], bf[8][2];
            #pragma unroll
            for (int mi = 0; mi < 2; mi++) {
                int mr = wm0 + mi*16 + grp;
                af[mi][0] = As[kk+qk  ][mr];
                af[mi][1] = As[kk+qk  ][mr+8];
                af[mi][2] = As[kk+qk+4][mr];
                af[mi][3] = As[kk+qk+4][mr+8];
            }
            #pragma unroll
            for (int ni = 0; ni < 8; ni++) {
                int nc = wn0 + ni*8 + grp;
                bf[ni][0] = Bs[kk+qk  ][nc];
                bf[ni][1] = Bs[kk+qk+4][nc];
            }
            #pragma unroll
            for (int mi = 0; mi < 2; mi++)
                #pragma unroll
                for (int ni = 0; ni < 8; ni++) {
                    asm volatile(
                        "mma.sync.aligned.m16n8k8.row.col.f32.tf32.tf32.f32 "
                        "{%0,%1,%2,%3}, {%4,%5,%6,%7}, {%8,%9}, {%0,%1,%2,%3};"
                        : "+f"(acc[mi][ni][0]), "+f"(acc[mi][ni][1]),
                          "+f"(acc[mi][ni][2]), "+f"(acc[mi][ni][3])
                        : "r"(af[mi][0]), "r"(af[mi][1]), "r"(af[mi][2]), "r"(af[mi][3]),
                          "r"(bf[ni][0]), "r"(bf[ni][1]));
                }
        }
        __syncthreads();
    }

    // epilogue: c0:(row, col) c1:(row, col+1) c2:(row+8, col) c3:(row+8, col+1)
    #pragma unroll
    for (int mi = 0; mi < 2; mi++) {
        #pragma unroll
        for (int ni = 0; ni < 8; ni++) {
            #pragma unroll
            for (int q = 0; q < 4; q++) {
                int m = m0 + wm0 + mi*16 + grp + ((q >> 1) << 3);
                int n = n0 + wn0 + ni*8 + (qk << 1) + (q & 1);
                float v = acc[mi][ni][q];
                if (MODE == 0) {
                    int which = n / CDIM;
                    int rem   = n - which * CDIM;
                    if (which == 0) v += bias[rem];
                    else if (which == 2) v += bias2[rem];
                    int bw = m >> 6, tok = m & 63;
                    int head = rem >> 5, dd = rem & 31;
                    C[which*QS + (((bw*HEADS) + head)*NTOK + tok)*HDIM + dd] = v;
                } else if (MODE == 1) {
                    v += bias[n];
                    C[(size_t)winperm(m) * N + n] = v;
                } else if (MODE == 2) {
                    v += bias[n];
                    C[(size_t)m * N + n] = v;
                } else {
                    v += bias[n];
                    v = 0.5f * v * (1.0f + erff(v * 0.70710678118654752f));
                    C[(size_t)m * N + n] = v;
                }
            }
        }
    }
}

// ---------------- fused attention: one block per (window, head) ----------------
__global__ void __launch_bounds__(64)
attn_kernel(const float* __restrict__ flex) {
    int b = blockIdx.x;
    int h = blockIdx.y;
    int n = threadIdx.x;

    __shared__ float kn[NTOK][HDIM+1];
    __shared__ float vs[NTOK][HDIM+1];
    __shared__ int   grp[NTOK];
    __shared__ float sscale;

    size_t base = ((size_t)(b*HEADS + h)) * NTOK * HDIM;
    const float* qp = g_qkv + base;
    const float* kp = g_qkv + QS   + base;
    const float* vp = g_qkv + 2*QS + base;

    float qr[HDIM];
    float qn2 = 0.f;
    #pragma unroll
    for (int d = 0; d < HDIM; d++) { qr[d] = qp[n*HDIM + d]; qn2 += qr[d]*qr[d]; }
    float qinv = 1.0f / fmaxf(sqrtf(qn2), 1e-12f);
    #pragma unroll
    for (int d = 0; d < HDIM; d++) qr[d] *= qinv;

    float kn2 = 0.f;
    float kr[HDIM];
    #pragma unroll
    for (int d = 0; d < HDIM; d++) { kr[d] = kp[n*HDIM + d]; kn2 += kr[d]*kr[d]; }
    float kinv = 1.0f / fmaxf(sqrtf(kn2), 1e-12f);
    #pragma unroll
    for (int d = 0; d < HDIM; d++) kn[n][d] = kr[d] * kinv;
    #pragma unroll
    for (int d = 0; d < HDIM; d++) vs[n][d] = vp[n*HDIM + d];

    {
        int w = b & 63;
        int hh = (w >> 3) * 8 + (n >> 3);
        int ww = (w & 7) * 8 + (n & 7);
        grp[n] = lab(hh) * 3 + lab(ww);
    }
    if (n == 0) sscale = expf(fminf(flex[h], 4.6051701859880914f));
    __syncthreads();

    float scale = sscale;
    int g1 = grp[n];
    const float* rp = g_rpb + (h*NTOK + n)*NTOK;

    float s[NTOK];
    float mx = -1e30f;
    #pragma unroll
    for (int m = 0; m < NTOK; m++) {
        float dot = 0.f;
        #pragma unroll
        for (int d = 0; d < HDIM; d++) dot += qr[d] * kn[m][d];
        float val = dot * scale + rp[m] + (grp[m] == g1 ? 0.f : -100.f);
        s[m] = val;
        mx = fmaxf(mx, val);
    }
    float sum = 0.f;
    #pragma unroll
    for (int m = 0; m < NTOK; m++) { s[m] = expf(s[m] - mx); sum += s[m]; }
    float inv = 1.0f / sum;

    float o[HDIM];
    #pragma unroll
    for (int d = 0; d < HDIM; d++) o[d] = 0.f;
    #pragma unroll
    for (int m = 0; m < NTOK; m++) {
        float p = s[m] * inv;
        #pragma unroll
        for (int d = 0; d < HDIM; d++) o[d] += p * vs[m][d];
    }

    float* dst = g_ao + (size_t)(b*NTOK + n) * CDIM + h*HDIM;
    #pragma unroll
    for (int d = 0; d < HDIM; d++) dst[d] = o[d];
}

// ---------------- residual + layernorm: out = res + LN(y)*g + b ----------------
__global__ void __launch_bounds__(128)
ln_add_kernel(const float* __restrict__ y, const float* __restrict__ res,
              const float* __restrict__ g, const float* __restrict__ b,
              float* __restrict__ out) {
    int row = blockIdx.x;
    int t = threadIdx.x;
    const float* yr = y + (size_t)row * CDIM;
    float v[3];
    float s = 0.f;
    #pragma unroll
    for (int i = 0; i < 3; i++) { v[i] = yr[t + i*128]; s += v[i]; }

    __shared__ float sh[5];
    int lane = t & 31, wid = t >> 5;
    #pragma unroll
    for (int o = 16; o > 0; o >>= 1) s += __shfl_down_sync(0xffffffffu, s, o);
    if (lane == 0) sh[wid] = s;
    __syncthreads();
    if (t == 0) sh[4] = sh[0] + sh[1] + sh[2] + sh[3];
    __syncthreads();
    float mean = sh[4] * (1.0f / CDIM);

    float s2 = 0.f;
    #pragma unroll
    for (int i = 0; i < 3; i++) { float d = v[i] - mean; s2 += d*d; }
    __syncthreads();
    #pragma unroll
    for (int o = 16; o > 0; o >>= 1) s2 += __shfl_down_sync(0xffffffffu, s2, o);
    if (lane == 0) sh[wid] = s2;
    __syncthreads();
    if (t == 0) sh[4] = sh[0] + sh[1] + sh[2] + sh[3];
    __syncthreads();
    float rstd = rsqrtf(sh[4] * (1.0f / CDIM) + 1e-5f);

    const float* rr = res + (size_t)row * CDIM;
    float* orow = out + (size_t)row * CDIM;
    #pragma unroll
    for (int i = 0; i < 3; i++) {
        int col = t + i*128;
        orow[col] = rr[col] + (v[i] - mean) * rstd * g[col] + b[col];
    }
}

// ---------------- launch ----------------
extern "C" void kernel_launch(void* const* d_in, const int* in_sizes, int n_in,
                              void* d_out, int out_size) {
    const float* x      = (const float*)d_in[0];
    const float* qkv_w  = (const float*)d_in[1];
    const float* q_bias = (const float*)d_in[2];
    const float* v_bias = (const float*)d_in[3];
    const float* flex   = (const float*)d_in[4];
    const float* cpb_w1 = (const float*)d_in[5];
    const float* cpb_b1 = (const float*)d_in[6];
    const float* cpb_w2 = (const float*)d_in[7];
    const float* proj_w = (const float*)d_in[8];
    const float* proj_b = (const float*)d_in[9];
    const float* n1g    = (const float*)d_in[10];
    const float* n1b    = (const float*)d_in[11];
    const float* n2g    = (const float*)d_in[12];
    const float* n2b    = (const float*)d_in[13];
    const float* fc1w   = (const float*)d_in[14];
    const float* fc1b   = (const float*)d_in[15];
    const float* fc2w   = (const float*)d_in[16];
    const float* fc2b   = (const float*)d_in[17];
    float* out = (float*)d_out;

    float *p_qkv, *p_ao, *p_tmp, *p_x1, *p_h;
    cudaGetSymbolAddress((void**)&p_qkv, g_qkv);
    cudaGetSymbolAddress((void**)&p_ao,  g_ao);
    cudaGetSymbolAddress((void**)&p_tmp, g_tmp);
    cudaGetSymbolAddress((void**)&p_x1,  g_x1);
    cudaGetSymbolAddress((void**)&p_h,   g_h);

    rpb_kernel<<<1, 256>>>(cpb_w1, cpb_b1, cpb_w2);

    // roll + partition + QKV (tf32)
    tgemm<0, true><<<dim3(NQKV/128, MTOK/128), 256>>>(
        x, qkv_w, q_bias, v_bias, p_qkv, MTOK, NQKV, CDIM);

    attn_kernel<<<dim3(BW, HEADS), 64>>>(flex);

    // proj + window reverse (tf32)
    tgemm<1, false><<<dim3(CDIM/128, MTOK/128), 256>>>(
        p_ao, proj_w, proj_b, nullptr, p_tmp, MTOK, CDIM, CDIM);

    ln_add_kernel<<<MTOK, 128>>>(p_tmp, x, n1g, n1b, p_x1);

    // fc1 + gelu (tf32)
    tgemm<3, false><<<dim3(HID/128, MTOK/128), 256>>>(
        p_x1, fc1w, fc1b, nullptr, p_h, MTOK, HID, CDIM);

    // fc2 (tf32)
    tgemm<2, false><<<dim3(CDIM/128, MTOK/128), 256>>>(
        p_h, fc2w, fc2b, nullptr, p_tmp, MTOK, CDIM, HID);

    ln_add_kernel<<<MTOK, 128>>>(p_tmp, p_x1, n2g, n2b, out);
}